// round 6
// baseline (speedup 1.0000x reference)
#include <cuda_runtime.h>

typedef unsigned long long u64;

__device__ __forceinline__ u64 ffma2(u64 a, u64 b, u64 c) {
    u64 d;
    asm("fma.rn.f32x2 %0, %1, %2, %3;" : "=l"(d) : "l"(a), "l"(b), "l"(c));
    return d;
}
__device__ __forceinline__ u64 pack2(float lo, float hi) {
    u64 d;
    asm("mov.b64 %0, {%1, %2};" : "=l"(d) : "f"(lo), "f"(hi));
    return d;
}
__device__ __forceinline__ float2 unpack2(u64 v) {
    float2 r;
    asm("mov.b64 {%0, %1}, %2;" : "=f"(r.x), "=f"(r.y) : "l"(v));
    return r;
}
union F4U { float4 f; u64 u[2]; };

// ---------------- static device scratch (no allocations allowed) -------------
__device__ float g_pool1[640 * 32 * 144];       // (640,32,12,12)
__device__ float g_pool2[640 * 1024];           // (640,64,4,4) flattened
__device__ float g_e[640 * 64];                 // e[b,k,d]
__device__ float g_S[16 * 64];
__device__ float g_S2[16 * 64];
__device__ float g_S3[16 * 64];
__device__ float g_f7[16 * 64];                 // S3·W7 + b1
__device__ float g_z[65536000];                 // 262 MB: relu(eq1) (16,40,40,40,64)
__device__ float g_zskp[16 * 1600 * 256];       // zsk partials: [b][i][j][grp][d]
__device__ float g_zsi[16 * 1600 * 64];         // sum over i: [b][j][k][d]
__device__ float g_zsj[16 * 1600 * 64];         // sum over j: [b][i][k][d]
__device__ float g_c1[16 * 1600 * 32];          // [b][j][k][o]
__device__ float g_c2[16 * 1600 * 32];          // [b][i][k][o]
__device__ float g_c3[16 * 1600 * 32];          // [b][i][j][o]
__device__ float g_c4[16 * 40 * 32];            // [b][k][o]
__device__ float g_c5[16 * 40 * 32];            // [b][j][o]
__device__ float g_c6[16 * 40 * 32];            // [b][i][o]
__device__ float g_c7[16 * 32];                 // [b][o]
__device__ float g_part[16 * 40 * 32];          // per-(b,i) sum_{j,k} relu(y2)

// ---------------- K1: conv1 (1->32, 5x5) + relu + maxpool2 ------------------
__global__ void k_conv1(const float* __restrict__ x,
                        const float* __restrict__ wgt,
                        const float* __restrict__ bias) {
    int n = blockIdx.x;                    // 0..639
    __shared__ float img[784];
    for (int t = threadIdx.x; t < 784; t += 256) img[t] = x[n * 784 + t];
    int c = threadIdx.x >> 3;              // 0..31 (out channel)
    int s = threadIdx.x & 7;
    float wr[25];
#pragma unroll
    for (int q = 0; q < 25; q++) wr[q] = wgt[c * 25 + q];
    float bv = bias[c];
    __syncthreads();
    for (int r = 0; r < 18; r++) {
        int p = s + (r << 3);              // 0..143 pooled position
        int py = p / 12, px = p % 12;
        float m = -1e30f;
#pragma unroll
        for (int dy = 0; dy < 2; dy++)
#pragma unroll
            for (int dx = 0; dx < 2; dx++) {
                int y = 2 * py + dy, xx = 2 * px + dx;
                float a = bv;
#pragma unroll
                for (int ky = 0; ky < 5; ky++)
#pragma unroll
                    for (int kx = 0; kx < 5; kx++)
                        a = fmaf(img[(y + ky) * 28 + xx + kx], wr[ky * 5 + kx], a);
                m = fmaxf(m, a);
            }
        g_pool1[n * 4608 + c * 144 + p] = fmaxf(m, 0.f);
    }
}

// ---------------- K2: conv2 (32->64, 5x5) + relu + maxpool2, packed ---------
__global__ void k_conv2(const float* __restrict__ wgt,
                        const float* __restrict__ bias) {
    int n = blockIdx.x;                    // 0..639
    __shared__ __align__(16) float in_sh[4608];   // 32 x 12 x 12
    __shared__ float ws[6400];             // 64 oc x 4 ic x 25
    for (int t = threadIdx.x; t < 4608; t += 256) in_sh[t] = g_pool1[n * 4608 + t];
    int oc = threadIdx.x >> 2;             // 0..63
    int py = threadIdx.x & 3;              // pooled row 0..3
    float bv = bias[oc];
    u64 acc2[8];                           // (conv row 2py, conv row 2py+1) per col
#pragma unroll
    for (int t = 0; t < 8; t++) acc2[t] = pack2(bv, bv);

    for (int icc = 0; icc < 8; icc++) {    // 4 input channels per chunk
        __syncthreads();
        for (int t = threadIdx.x; t < 6400; t += 256) {
            int oo = t / 100;
            int rem = t % 100;             // icl*25 + q
            ws[t] = wgt[oo * 800 + icc * 100 + rem];
        }
        __syncthreads();
#pragma unroll
        for (int icl = 0; icl < 4; icl++) {
            const float* ip = &in_sh[(icc * 4 + icl) * 144];
            const float* wp = &ws[oc * 100 + icl * 25];
#pragma unroll
            for (int ky = 0; ky < 5; ky++) {
                const float4* pr = reinterpret_cast<const float4*>(ip + (2 * py + ky) * 12);
                float4 A0 = pr[0], A1 = pr[1], A2 = pr[2], A3 = pr[3], A4 = pr[4], A5 = pr[5];
                float r[24] = {A0.x, A0.y, A0.z, A0.w, A1.x, A1.y, A1.z, A1.w,
                               A2.x, A2.y, A2.z, A2.w, A3.x, A3.y, A3.z, A3.w,
                               A4.x, A4.y, A4.z, A4.w, A5.x, A5.y, A5.z, A5.w};
                u64 rp[12];
#pragma unroll
                for (int t = 0; t < 12; t++) rp[t] = pack2(r[t], r[t + 12]);
#pragma unroll
                for (int kx = 0; kx < 5; kx++) {
                    float wv = wp[ky * 5 + kx];
                    u64 w2 = pack2(wv, wv);
#pragma unroll
                    for (int cx = 0; cx < 8; cx++)
                        acc2[cx] = ffma2(rp[cx + kx], w2, acc2[cx]);
                }
            }
        }
    }
#pragma unroll
    for (int px = 0; px < 4; px++) {
        float2 a = unpack2(acc2[2 * px]);
        float2 bq = unpack2(acc2[2 * px + 1]);
        float m = fmaxf(fmaxf(a.x, a.y), fmaxf(bq.x, bq.y));
        g_pool2[n * 1024 + oc * 16 + py * 4 + px] = fmaxf(m, 0.f);
    }
}

// ---------------- K3: fc (1024->64) + relu ----------------------------------
__global__ void k_fc(const float* __restrict__ fw, const float* __restrict__ fb) {
    int n0 = blockIdx.x * 4;               // 4 images per block
    __shared__ float in_sh[4096];
    for (int t = threadIdx.x; t < 4096; t += 256) in_sh[t] = g_pool2[n0 * 1024 + t];
    __syncthreads();
    int o = threadIdx.x & 63, im = threadIdx.x >> 6;
    const float* irow = &in_sh[im * 1024];
    float acc = fb[o];
#pragma unroll 8
    for (int t = 0; t < 1024; t++) acc = fmaf(irow[t], fw[t * 64 + o], acc);
    g_e[(n0 + im) * 64 + o] = fmaxf(acc, 0.f);
}

// ---------------- K3b: S, S^2, S^3 ------------------------------------------
__global__ void k_S() {
    int b = blockIdx.x, d = threadIdx.x;   // 16 x 64
    float s = 0.f;
#pragma unroll
    for (int t = 0; t < 40; t++) s += g_e[(b * 40 + t) * 64 + d];
    g_S[b * 64 + d] = s;
    g_S2[b * 64 + d] = s * s;
    g_S3[b * 64 + d] = s * s * s;
}

// ---------------- K3c: f7[b,o] = sum_d S3*W7 + b1 ---------------------------
__global__ void k_pre1(const float* __restrict__ W, const float* __restrict__ b1) {
    int b = blockIdx.x, o = threadIdx.x;   // 16 x 64
    const float* W7 = W + 7 * 4096;
    float acc = b1[o];
#pragma unroll 8
    for (int d = 0; d < 64; d++) acc = fmaf(g_S3[b * 64 + d], W7[d * 64 + o], acc);
    g_f7[b * 64 + o] = acc;
}

// ---------------- K4: eq1 layer, block per (b,i), packed f32x2 --------------
__global__ void __launch_bounds__(256, 2)
k_eq1(const float* __restrict__ W) {
    int i = blockIdx.x, b = blockIdx.y;
    __shared__ __align__(16) float she[2560];   // e[b] (40 x 64)
    __shared__ __align__(16) float shT[4096];   // B/U/A in setup; X_j in main loop
    __shared__ __align__(16) float shG[2560];
    __shared__ __align__(16) float shF[2560];
    __shared__ float shS[64], shS2[64], shEi[64], shBase[64];

    int tid = threadIdx.x;
    const float* eb = g_e + b * 2560;
    for (int t = tid; t < 2560; t += 256) she[t] = eb[t];
    if (tid < 64) {
        shS[tid] = g_S[b * 64 + tid];
        shS2[tid] = g_S2[b * 64 + tid];
        shEi[tid] = eb[i * 64 + tid];
    }
    __syncthreads();

    const float* W0 = W;
    const float* W1 = W + 4096;
    const float* W2 = W + 2 * 4096;
    const float* W3 = W + 3 * 4096;
    const float* W4 = W + 4 * 4096;
    const float* W5 = W + 5 * 4096;
    const float* W6 = W + 6 * 4096;

    int o = tid & 63, grp = tid >> 6;      // 4 groups of 10

    // B_i into shT ; base into shBase
    for (int idx = tid; idx < 4096; idx += 256) {
        int d = idx >> 6;
        shT[idx] = shS[d] * shEi[d] * W2[idx] + shS2[d] * W4[idx];
    }
    if (tid < 64) {
        float a = g_f7[b * 64 + tid];
#pragma unroll 8
        for (int d = 0; d < 64; d++)
            a = fmaf(shS2[d] * shEi[d], W6[d * 64 + tid], a);
        shBase[tid] = a;
    }
    __syncthreads();
    // G = e @ B (packed)
    {
        u64 T2[32];
#pragma unroll
        for (int q = 0; q < 32; q++)
            T2[q] = pack2(shT[(2 * q) * 64 + o], shT[(2 * q + 1) * 64 + o]);
        for (int kk = 0; kk < 10; kk++) {
            int k = grp * 10 + kk;
            const F4U* x4 = reinterpret_cast<const F4U*>(&she[k * 64]);
            u64 acc2 = pack2(0.f, 0.f);
#pragma unroll
            for (int q = 0; q < 16; q++) {
                F4U v = x4[q];
                acc2 = ffma2(v.u[0], T2[2 * q], acc2);
                acc2 = ffma2(v.u[1], T2[2 * q + 1], acc2);
            }
            float2 rr = unpack2(acc2);
            shG[k * 64 + o] = rr.x + rr.y;
        }
    }
    __syncthreads();
    // U_i into shT
    for (int idx = tid; idx < 4096; idx += 256) {
        int d = idx >> 6;
        shT[idx] = shS[d] * shEi[d] * W3[idx] + shS2[d] * W5[idx];
    }
    __syncthreads();
    // F = e @ U + base (packed)
    {
        u64 T2[32];
#pragma unroll
        for (int q = 0; q < 32; q++)
            T2[q] = pack2(shT[(2 * q) * 64 + o], shT[(2 * q + 1) * 64 + o]);
        for (int jj = 0; jj < 10; jj++) {
            int j = grp * 10 + jj;
            const F4U* x4 = reinterpret_cast<const F4U*>(&she[j * 64]);
            u64 acc2 = pack2(shBase[o], 0.f);
#pragma unroll
            for (int q = 0; q < 16; q++) {
                F4U v = x4[q];
                acc2 = ffma2(v.u[0], T2[2 * q], acc2);
                acc2 = ffma2(v.u[1], T2[2 * q + 1], acc2);
            }
            float2 rr = unpack2(acc2);
            shF[j * 64 + o] = rr.x + rr.y;
        }
    }
    __syncthreads();
    // A_i into shT, then packed registers
    for (int idx = tid; idx < 4096; idx += 256) {
        int d = idx >> 6;
        shT[idx] = shEi[d] * W0[idx] + shS[d] * W1[idx];
    }
    __syncthreads();
    u64 A2[32];
#pragma unroll
    for (int q = 0; q < 32; q++)
        A2[q] = pack2(shT[(2 * q) * 64 + o], shT[(2 * q + 1) * 64 + o]);
    __syncthreads();                       // all A2 read before shT reused as X

    float zsjacc[10];
#pragma unroll
    for (int q = 0; q < 10; q++) zsjacc[q] = 0.f;

    long long zbi = ((long long)(b * 40 + i)) * 40 * 2560;
    long long skp = ((long long)(b * 40 + i)) * 40 * 256;
    for (int j = 0; j < 40; j++) {
        // X_j[k,d] = e_j[d] * e_k[d] into shT[0..2560)
        for (int t = tid; t < 2560; t += 256) {
            int kx = t >> 6, dx = t & 63;
            shT[t] = she[j * 64 + dx] * she[kx * 64 + dx];
        }
        __syncthreads();
        float cfj = shF[j * 64 + o];
        float zrow = 0.f;
        float* zp = g_z + zbi + (long long)j * 2560;
        for (int kk = 0; kk < 10; kk++) {
            int k = grp * 10 + kk;
            const F4U* x4 = reinterpret_cast<const F4U*>(&shT[k * 64]);
            u64 acc2 = pack2(cfj + shG[k * 64 + o], 0.f);
#pragma unroll
            for (int q = 0; q < 16; q++) {
                F4U v = x4[q];
                acc2 = ffma2(v.u[0], A2[2 * q], acc2);
                acc2 = ffma2(v.u[1], A2[2 * q + 1], acc2);
            }
            float2 rr = unpack2(acc2);
            float zv = fmaxf(rr.x + rr.y, 0.f);
            __stcs(zp + k * 64 + o, zv);
            zrow += zv;
            zsjacc[kk] += zv;
        }
        g_zskp[skp + (long long)j * 256 + tid] = zrow;   // per-warp-group partial
        __syncthreads();                   // WAR: shT refilled next j
    }
#pragma unroll
    for (int kk = 0; kk < 10; kk++) {
        int k = grp * 10 + kk;
        g_zsj[((b * 40 + i) * 40 + k) * 64 + o] = zsjacc[kk];
    }
}

// ---------------- K5: zsi = sum over i of z (coalesced stream) --------------
__global__ void k_sums() {
    int j = blockIdx.x, b = blockIdx.y;    // grid (40,16)
    int tid = threadIdx.x;
    float acc[10];
#pragma unroll
    for (int q = 0; q < 10; q++) acc[q] = 0.f;
    for (int i = 0; i < 40; i++) {
        const float* p = g_z + (((long long)((b * 40 + i) * 40 + j)) * 2560);
#pragma unroll
        for (int q = 0; q < 10; q++) acc[q] += __ldcs(p + tid + q * 256);
    }
    float* dst = g_zsi + ((long long)(b * 40 + j)) * 2560;
#pragma unroll
    for (int q = 0; q < 10; q++) dst[tid + q * 256] = acc[q];
}

// ---------------- K5b: c1/c2/c3 = zsum_* @ V_m ------------------------------
__global__ void k_cproj(const float* __restrict__ V, int which) {
    float* dst = (which == 0) ? g_c1 : (which == 1) ? g_c2 : g_c3;
    const float* Wm = V + (which + 1) * 2048;   // V1 / V2 / V3
    __shared__ float rows[512];            // 8 rows x 64
    __shared__ float ws[2048];             // 64 x 32
    int r0 = blockIdx.x * 8;
    for (int t = threadIdx.x; t < 2048; t += 256) ws[t] = Wm[t];
    if (which == 2) {
        for (int t = threadIdx.x; t < 512; t += 256) {
            int rr = t >> 6, d = t & 63;
            const float* p = g_zskp + (long long)(r0 + rr) * 256 + d;
            rows[t] = p[0] + p[64] + p[128] + p[192];
        }
    } else {
        const float* src = (which == 0) ? g_zsi : g_zsj;
        for (int t = threadIdx.x; t < 512; t += 256) rows[t] = src[r0 * 64 + t];
    }
    __syncthreads();
    int o = threadIdx.x & 31, rr = threadIdx.x >> 5;
    float acc = 0.f;
#pragma unroll
    for (int d = 0; d < 64; d++) acc = fmaf(rows[rr * 64 + d], ws[d * 32 + o], acc);
    dst[(r0 + rr) * 32 + o] = acc;
}

// ---------------- K5c: pair/total sums -> c4..c7 ----------------------------
__global__ void k_cpair(const float* __restrict__ V) {
    int b = blockIdx.x;                    // 16 blocks, 256 threads
    __shared__ float zij[2560];            // [k][d]
    __shared__ float zik[2560];            // [j][d]
    __shared__ float zjk[2560];            // [i][d]
    __shared__ float zs[64];
    int d = threadIdx.x & 63, g = threadIdx.x >> 6;
    for (int q = 0; q < 10; q++) {
        int k = g * 10 + q;
        float s = 0.f;
#pragma unroll 8
        for (int j = 0; j < 40; j++) s += g_zsi[((b * 40 + j) * 40 + k) * 64 + d];
        zij[k * 64 + d] = s;
    }
    for (int q = 0; q < 10; q++) {
        int j = g * 10 + q;
        float s = 0.f;
#pragma unroll 8
        for (int k = 0; k < 40; k++) s += g_zsi[((b * 40 + j) * 40 + k) * 64 + d];
        zik[j * 64 + d] = s;
    }
    for (int q = 0; q < 10; q++) {
        int i = g * 10 + q;
        float s = 0.f;
#pragma unroll 8
        for (int k = 0; k < 40; k++) s += g_zsj[((b * 40 + i) * 40 + k) * 64 + d];
        zjk[i * 64 + d] = s;
    }
    __syncthreads();
    if (threadIdx.x < 64) {
        float s = 0.f;
#pragma unroll
        for (int k = 0; k < 40; k++) s += zij[k * 64 + threadIdx.x];
        zs[threadIdx.x] = s;
    }
    __syncthreads();
    const float* V4 = V + 4 * 2048;
    const float* V5 = V + 5 * 2048;
    const float* V6 = V + 6 * 2048;
    const float* V7 = V + 7 * 2048;
    int o = threadIdx.x & 31, kg = threadIdx.x >> 5;   // 8 groups of 5
    for (int q = 0; q < 5; q++) {
        int k = kg * 5 + q;
        float a4 = 0.f, a5 = 0.f, a6 = 0.f;
#pragma unroll 8
        for (int dd = 0; dd < 64; dd++) {
            a4 = fmaf(zij[k * 64 + dd], V4[dd * 32 + o], a4);
            a5 = fmaf(zik[k * 64 + dd], V5[dd * 32 + o], a5);
            a6 = fmaf(zjk[k * 64 + dd], V6[dd * 32 + o], a6);
        }
        g_c4[(b * 40 + k) * 32 + o] = a4;
        g_c5[(b * 40 + k) * 32 + o] = a5;
        g_c6[(b * 40 + k) * 32 + o] = a6;
    }
    if (threadIdx.x < 32) {
        float a = 0.f;
#pragma unroll 8
        for (int dd = 0; dd < 64; dd++) a = fmaf(zs[dd], V7[dd * 32 + threadIdx.x], a);
        g_c7[b * 32 + threadIdx.x] = a;
    }
}

// ---------------- K6: eq2 + relu + sum over j,k, block per (b,i), packed ----
__global__ void __launch_bounds__(256, 2)
k_eq2(const float* __restrict__ V, const float* __restrict__ b2) {
    int i = blockIdx.x, b = blockIdx.y;
    __shared__ __align__(16) float zbuf[2][2560];
    __shared__ float c1buf[2][1280];
    __shared__ float c2s[1280], c4s[1280];
    __shared__ float cb[32];
    __shared__ float red[256];
    int tid = threadIdx.x;
    for (int t = tid; t < 1280; t += 256) {
        c2s[t] = g_c2[(b * 40 + i) * 1280 + t];
        c4s[t] = g_c4[b * 1280 + t];
    }
    int o = tid & 31, kq = tid >> 5;       // 8 groups of 5 k
    if (tid < 32)
        cb[tid] = g_c6[(b * 40 + i) * 32 + tid] + g_c7[b * 32 + tid] + b2[tid];
    u64 V2[32];
#pragma unroll
    for (int q = 0; q < 32; q++)
        V2[q] = pack2(V[(2 * q) * 32 + o], V[(2 * q + 1) * 32 + o]);   // V0 column o

    long long zbi = ((long long)(b * 40 + i)) * 40 * 2560;
    const float* c3p = g_c3 + (b * 40 + i) * 1280;
    const float* c5p = g_c5 + b * 1280;

    // prologue: j = 0 tiles + c3/c5 for j=0
    {
        const float* zp = g_z + zbi;
        const float* c1p = g_c1 + (b * 40) * 1280;
#pragma unroll
        for (int q = 0; q < 10; q++) zbuf[0][tid + q * 256] = __ldcs(zp + tid + q * 256);
#pragma unroll
        for (int q = 0; q < 5; q++) c1buf[0][tid + q * 256] = c1p[tid + q * 256];
    }
    float cf_cur = c3p[o] + c5p[o];
    __syncthreads();

    float part = 0.f;
    for (int j = 0; j < 40; j++) {
        int cur = j & 1;
        float rz[10], rc[5], cf_next = 0.f;
        if (j < 39) {                       // prefetch j+1 into registers
            const float* zp = g_z + zbi + (long long)(j + 1) * 2560;
            const float* c1p = g_c1 + (b * 40 + j + 1) * 1280;
#pragma unroll
            for (int q = 0; q < 10; q++) rz[q] = __ldcs(zp + tid + q * 256);
#pragma unroll
            for (int q = 0; q < 5; q++) rc[q] = c1p[tid + q * 256];
            cf_next = c3p[(j + 1) * 32 + o] + c5p[(j + 1) * 32 + o];
        }
        float cf = cb[o] + cf_cur;
        for (int q = 0; q < 5; q++) {
            int k = kq * 5 + q;
            const F4U* z4 = reinterpret_cast<const F4U*>(&zbuf[cur][k * 64]);
            u64 acc2 = pack2(cf + c1buf[cur][k * 32 + o] + c2s[k * 32 + o]
                                + c4s[k * 32 + o], 0.f);
#pragma unroll
            for (int t = 0; t < 16; t++) {
                F4U v = z4[t];
                acc2 = ffma2(v.u[0], V2[2 * t], acc2);
                acc2 = ffma2(v.u[1], V2[2 * t + 1], acc2);
            }
            float2 rr = unpack2(acc2);
            part += fmaxf(rr.x + rr.y, 0.f);
        }
        if (j < 39) {                       // commit prefetch to other buffer
#pragma unroll
            for (int q = 0; q < 10; q++) zbuf[cur ^ 1][tid + q * 256] = rz[q];
#pragma unroll
            for (int q = 0; q < 5; q++) c1buf[cur ^ 1][tid + q * 256] = rc[q];
            cf_cur = cf_next;
        }
        __syncthreads();
    }
    red[tid] = part;
    __syncthreads();
    if (tid < 32) {
        float s = 0.f;
#pragma unroll
        for (int g = 0; g < 8; g++) s += red[g * 32 + tid];
        g_part[(b * 40 + i) * 32 + tid] = s;
    }
}

// ---------------- K7: final reduce + out projection -------------------------
__global__ void k_final(const float* __restrict__ ow, const float* __restrict__ ob,
                        float* __restrict__ out) {
    int b = blockIdx.x;                    // 16 blocks, 256 threads
    __shared__ float red[256];
    int o = threadIdx.x & 31, g = threadIdx.x >> 5;
    float s = 0.f;
    for (int i = g; i < 40; i += 8) s += g_part[(b * 40 + i) * 32 + o];
    red[threadIdx.x] = s;
    __syncthreads();
    if (threadIdx.x < 32) {
        float tot = 0.f;
#pragma unroll
        for (int q = 0; q < 8; q++) tot += red[q * 32 + threadIdx.x];
        tot = fmaxf(tot, 0.f);
        float v = tot * ow[threadIdx.x];
#pragma unroll
        for (int off = 16; off; off >>= 1) v += __shfl_down_sync(0xffffffffu, v, off);
        if (threadIdx.x == 0) out[b] = v + ob[0];
    }
}

// ---------------- launcher ---------------------------------------------------
extern "C" void kernel_launch(void* const* d_in, const int* in_sizes, int n_in,
                              void* d_out, int out_size) {
    const float* x   = (const float*)d_in[0];
    const float* c1w = (const float*)d_in[1];
    const float* c1b = (const float*)d_in[2];
    const float* c2w = (const float*)d_in[3];
    const float* c2b = (const float*)d_in[4];
    const float* fcw = (const float*)d_in[5];
    const float* fcb = (const float*)d_in[6];
    const float* e1w = (const float*)d_in[7];
    const float* e1b = (const float*)d_in[8];
    const float* e2w = (const float*)d_in[9];
    const float* e2b = (const float*)d_in[10];
    const float* ow  = (const float*)d_in[11];
    const float* ob  = (const float*)d_in[12];
    float* out = (float*)d_out;

    k_conv1<<<640, 256>>>(x, c1w, c1b);
    k_conv2<<<640, 256>>>(c2w, c2b);
    k_fc<<<160, 256>>>(fcw, fcb);
    k_S<<<16, 64>>>();
    k_pre1<<<16, 64>>>(e1w, e1b);
    dim3 gbi(40, 16);
    k_eq1<<<gbi, 256>>>(e1w);
    k_sums<<<gbi, 256>>>();
    k_cproj<<<3200, 256>>>(e2w, 0);
    k_cproj<<<3200, 256>>>(e2w, 1);
    k_cproj<<<3200, 256>>>(e2w, 2);
    k_cpair<<<16, 256>>>(e2w);
    k_eq2<<<gbi, 256>>>(e2w, e2b);
    k_final<<<16, 256>>>(ow, ob, out);
}

// round 7
// speedup vs baseline: 1.2748x; 1.2748x over previous
#include <cuda_runtime.h>

// ---------------- static device scratch (no allocations allowed) -------------
__device__ float g_pool1[640 * 32 * 144];       // (640,32,12,12)
__device__ float g_pool2[640 * 1024];           // (640,64,4,4) flattened
__device__ float g_e[640 * 64];                 // e[b,k,d]
__device__ float g_S[16 * 64];
__device__ float g_S2[16 * 64];
__device__ float g_S3[16 * 64];
__device__ float g_f7[16 * 64];                 // S3·W7 + b1
__device__ float g_z[65536000];                 // 262 MB: relu(eq1) (16,40,40,40,64)
__device__ float g_zsk[16 * 1600 * 64];         // sum over k: [b][i][j][d]
__device__ float g_zsi[16 * 1600 * 64];         // sum over i: [b][j][k][d]
__device__ float g_zsj[16 * 1600 * 64];         // sum over j: [b][i][k][d]
__device__ float g_c1[16 * 1600 * 32];          // [b][j][k][o]
__device__ float g_c2[16 * 1600 * 32];          // [b][i][k][o]
__device__ float g_c3[16 * 1600 * 32];          // [b][i][j][o]
__device__ float g_c4[16 * 40 * 32];            // [b][k][o]
__device__ float g_c5[16 * 40 * 32];            // [b][j][o]
__device__ float g_c6[16 * 40 * 32];            // [b][i][o]
__device__ float g_c7[16 * 32];                 // [b][o]
__device__ float g_part[16 * 40 * 32];          // per-(b,i) sum_{j,k} relu(y2)

__device__ __forceinline__ unsigned to_tf32(float f) {
    unsigned r;
    asm("cvt.rna.tf32.f32 %0, %1;" : "=r"(r) : "f"(f));
    return r;
}
__device__ __forceinline__ void mma_tf32(float* c, const unsigned* a, const unsigned* bq) {
    asm("mma.sync.aligned.m16n8k8.row.col.f32.tf32.tf32.f32 "
        "{%0,%1,%2,%3}, {%4,%5,%6,%7}, {%8,%9}, {%0,%1,%2,%3};"
        : "+f"(c[0]), "+f"(c[1]), "+f"(c[2]), "+f"(c[3])
        : "r"(a[0]), "r"(a[1]), "r"(a[2]), "r"(a[3]), "r"(bq[0]), "r"(bq[1]));
}

// ---------------- K1: conv1 (1->32, 5x5) + relu + maxpool2 ------------------
__global__ void k_conv1(const float* __restrict__ x,
                        const float* __restrict__ wgt,
                        const float* __restrict__ bias) {
    int n = blockIdx.x;                    // 0..639
    __shared__ float img[784];
    for (int t = threadIdx.x; t < 784; t += 256) img[t] = x[n * 784 + t];
    int c = threadIdx.x >> 3;              // 0..31 (out channel)
    int s = threadIdx.x & 7;
    float wr[25];
#pragma unroll
    for (int q = 0; q < 25; q++) wr[q] = wgt[c * 25 + q];
    float bv = bias[c];
    __syncthreads();
    for (int r = 0; r < 18; r++) {
        int p = s + (r << 3);              // 0..143 pooled position
        int py = p / 12, px = p % 12;
        float m = -1e30f;
#pragma unroll
        for (int dy = 0; dy < 2; dy++)
#pragma unroll
            for (int dx = 0; dx < 2; dx++) {
                int y = 2 * py + dy, xx = 2 * px + dx;
                float a = bv;
#pragma unroll
                for (int ky = 0; ky < 5; ky++)
#pragma unroll
                    for (int kx = 0; kx < 5; kx++)
                        a = fmaf(img[(y + ky) * 28 + xx + kx], wr[ky * 5 + kx], a);
                m = fmaxf(m, a);
            }
        g_pool1[n * 4608 + c * 144 + p] = fmaxf(m, 0.f);
    }
}

// ---------------- K2: conv2 (32->64, 5x5) + relu + maxpool2 -----------------
__global__ void k_conv2(const float* __restrict__ wgt,
                        const float* __restrict__ bias) {
    int n = blockIdx.x;                    // 0..639
    __shared__ float in_sh[4608];          // 32 x 12 x 12
    __shared__ float ws[6400];             // 64 oc x 4 ic x 25
    for (int t = threadIdx.x; t < 4608; t += 256) in_sh[t] = g_pool1[n * 4608 + t];
    int oc = threadIdx.x >> 2;             // 0..63
    int py = threadIdx.x & 3;              // pooled row 0..3
    float bv = bias[oc];
    float acc[16];
#pragma unroll
    for (int t = 0; t < 16; t++) acc[t] = bv;

    for (int icc = 0; icc < 8; icc++) {    // 4 input channels per chunk
        __syncthreads();
        for (int t = threadIdx.x; t < 6400; t += 256) {
            int oo = t / 100;
            int rem = t % 100;             // icl*25 + q
            ws[t] = wgt[oo * 800 + icc * 100 + rem];
        }
        __syncthreads();
#pragma unroll
        for (int icl = 0; icl < 4; icl++) {
            const float* ip = &in_sh[(icc * 4 + icl) * 144];
            const float* wp = &ws[oc * 100 + icl * 25];
#pragma unroll
            for (int ky = 0; ky < 5; ky++) {
                const float4* pr = reinterpret_cast<const float4*>(ip + (2 * py + ky) * 12);
                float4 A0 = pr[0], A1 = pr[1], A2 = pr[2], A3 = pr[3], A4 = pr[4], A5 = pr[5];
                float r[24] = {A0.x, A0.y, A0.z, A0.w, A1.x, A1.y, A1.z, A1.w,
                               A2.x, A2.y, A2.z, A2.w, A3.x, A3.y, A3.z, A3.w,
                               A4.x, A4.y, A4.z, A4.w, A5.x, A5.y, A5.z, A5.w};
#pragma unroll
                for (int kx = 0; kx < 5; kx++) {
                    float wv = wp[ky * 5 + kx];
#pragma unroll
                    for (int cx = 0; cx < 8; cx++) {
                        acc[cx]     = fmaf(r[cx + kx],      wv, acc[cx]);
                        acc[8 + cx] = fmaf(r[12 + cx + kx], wv, acc[8 + cx]);
                    }
                }
            }
        }
    }
#pragma unroll
    for (int px = 0; px < 4; px++) {
        float m = fmaxf(fmaxf(acc[2 * px], acc[2 * px + 1]),
                        fmaxf(acc[8 + 2 * px], acc[8 + 2 * px + 1]));
        g_pool2[n * 1024 + oc * 16 + py * 4 + px] = fmaxf(m, 0.f);
    }
}

// ---------------- K3: fc (1024->64) + relu ----------------------------------
__global__ void k_fc(const float* __restrict__ fw, const float* __restrict__ fb) {
    int n0 = blockIdx.x * 4;               // 4 images per block
    __shared__ float in_sh[4096];
    for (int t = threadIdx.x; t < 4096; t += 256) in_sh[t] = g_pool2[n0 * 1024 + t];
    __syncthreads();
    int o = threadIdx.x & 63, im = threadIdx.x >> 6;
    const float* irow = &in_sh[im * 1024];
    float acc = fb[o];
#pragma unroll 8
    for (int t = 0; t < 1024; t++) acc = fmaf(irow[t], fw[t * 64 + o], acc);
    g_e[(n0 + im) * 64 + o] = fmaxf(acc, 0.f);
}

// ---------------- K3b: S, S^2, S^3 ------------------------------------------
__global__ void k_S() {
    int b = blockIdx.x, d = threadIdx.x;   // 16 x 64
    float s = 0.f;
#pragma unroll
    for (int t = 0; t < 40; t++) s += g_e[(b * 40 + t) * 64 + d];
    g_S[b * 64 + d] = s;
    g_S2[b * 64 + d] = s * s;
    g_S3[b * 64 + d] = s * s * s;
}

// ---------------- K3c: f7[b,o] = sum_d S3*W7 + b1 ---------------------------
__global__ void k_pre1(const float* __restrict__ W, const float* __restrict__ b1) {
    int b = blockIdx.x, o = threadIdx.x;   // 16 x 64
    const float* W7 = W + 7 * 4096;
    float acc = b1[o];
#pragma unroll 8
    for (int d = 0; d < 64; d++) acc = fmaf(g_S3[b * 64 + d], W7[d * 64 + o], acc);
    g_f7[b * 64 + o] = acc;
}

// ---------------- K4: eq1 layer, block per (b,i), tensor-core tf32 ----------
// z[j] = E (40x64) @ diag(e_j) @ A_i (64x64), + G_i[k,o] + F_i[j,o], ReLU.
// E held in m16n8k8 tf32 A-fragments (M padded to 48), constant across j.
// Per j: rescale A_i columns by e_j into B-fragments, 24 mma per warp.
__global__ void __launch_bounds__(256, 1)
k_eq1(const float* __restrict__ W) {
    int i = blockIdx.x, b = blockIdx.y;
    __shared__ __align__(16) float she[2560];   // e[b] (40 x 64)
    __shared__ __align__(16) float shA[4224];   // temp [d*64+o] in setup; A^T [o*66+d] in main
    __shared__ __align__(16) float shG[2560];
    __shared__ __align__(16) float shF[2560];
    __shared__ float shS[64], shS2[64], shEi[64], shBase[64];

    int tid = threadIdx.x;
    const float* eb = g_e + b * 2560;
    for (int t = tid; t < 2560; t += 256) she[t] = eb[t];
    if (tid < 64) {
        shS[tid] = g_S[b * 64 + tid];
        shS2[tid] = g_S2[b * 64 + tid];
        shEi[tid] = eb[i * 64 + tid];
    }
    __syncthreads();

    const float* W0 = W;
    const float* W1 = W + 4096;
    const float* W2 = W + 2 * 4096;
    const float* W3 = W + 3 * 4096;
    const float* W4 = W + 4 * 4096;
    const float* W5 = W + 5 * 4096;
    const float* W6 = W + 6 * 4096;

    int o64 = tid & 63, grp = tid >> 6;    // 4 groups of 10

    // B_i into shA[d*64+o] ; base into shBase
    for (int idx = tid; idx < 4096; idx += 256) {
        int d = idx >> 6;
        shA[idx] = shS[d] * shEi[d] * W2[idx] + shS2[d] * W4[idx];
    }
    if (tid < 64) {
        float a = g_f7[b * 64 + tid];
#pragma unroll 8
        for (int d = 0; d < 64; d++)
            a = fmaf(shS2[d] * shEi[d], W6[d * 64 + tid], a);
        shBase[tid] = a;
    }
    __syncthreads();
    // G = e @ B
    for (int kk = 0; kk < 10; kk++) {
        int k = grp * 10 + kk;
        float acc = 0.f;
#pragma unroll 8
        for (int d = 0; d < 64; d++) acc = fmaf(she[k * 64 + d], shA[d * 64 + o64], acc);
        shG[k * 64 + o64] = acc;
    }
    __syncthreads();
    // U_i into shA
    for (int idx = tid; idx < 4096; idx += 256) {
        int d = idx >> 6;
        shA[idx] = shS[d] * shEi[d] * W3[idx] + shS2[d] * W5[idx];
    }
    __syncthreads();
    // F = e @ U + base
    for (int jj = 0; jj < 10; jj++) {
        int j = grp * 10 + jj;
        float acc = shBase[o64];
#pragma unroll 8
        for (int d = 0; d < 64; d++) acc = fmaf(she[j * 64 + d], shA[d * 64 + o64], acc);
        shF[j * 64 + o64] = acc;
    }
    __syncthreads();
    // A_i transposed: shA[o*66 + d]
    for (int idx = tid; idx < 4096; idx += 256) {
        int d = idx >> 6, o = idx & 63;
        shA[o * 66 + d] = shEi[d] * W0[idx] + shS[d] * W1[idx];
    }
    __syncthreads();

    // ---- fragment setup ----
    int lane = tid & 31, warp = tid >> 5;
    int g = lane >> 2, tg = lane & 3;      // groupID, threadInGroup
    int n0 = warp * 8;                     // this warp's 8 output cols
    int o0 = n0 + 2 * tg;

    unsigned Ea[3][8][4];                  // E fragments, M-tiles x K-tiles
#pragma unroll
    for (int m = 0; m < 3; m++)
#pragma unroll
        for (int kt = 0; kt < 8; kt++) {
            int r1 = 16 * m + g, r2 = r1 + 8;
            int cL = kt * 8 + tg, cH = cL + 4;
            Ea[m][kt][0] = to_tf32(she[r1 * 64 + cL]);
            Ea[m][kt][2] = to_tf32(she[r1 * 64 + cH]);
            Ea[m][kt][1] = (m < 2) ? to_tf32(she[r2 * 64 + cL]) : 0u;
            Ea[m][kt][3] = (m < 2) ? to_tf32(she[r2 * 64 + cH]) : 0u;
        }
    float Gr[3][4];
#pragma unroll
    for (int m = 0; m < 3; m++) {
        int r1 = 16 * m + g, r2 = r1 + 8;
        Gr[m][0] = shG[r1 * 64 + o0];
        Gr[m][1] = shG[r1 * 64 + o0 + 1];
        Gr[m][2] = (m < 2) ? shG[r2 * 64 + o0] : 0.f;
        Gr[m][3] = (m < 2) ? shG[r2 * 64 + o0 + 1] : 0.f;
    }
    float zj[3][4];
#pragma unroll
    for (int m = 0; m < 3; m++)
#pragma unroll
        for (int q = 0; q < 4; q++) zj[m][q] = 0.f;

    long long zbi = ((long long)(b * 40 + i)) * 40 * 2560;
    for (int j = 0; j < 40; j++) {
        unsigned Bf[8][2];
#pragma unroll
        for (int kt = 0; kt < 8; kt++) {
            float el = she[j * 64 + kt * 8 + tg];
            float eh = she[j * 64 + kt * 8 + tg + 4];
            Bf[kt][0] = to_tf32(shA[(n0 + g) * 66 + kt * 8 + tg] * el);
            Bf[kt][1] = to_tf32(shA[(n0 + g) * 66 + kt * 8 + tg + 4] * eh);
        }
        float f0 = shF[j * 64 + o0], f1 = shF[j * 64 + o0 + 1];
        float* zp = g_z + zbi + (long long)j * 2560;
        float p0 = 0.f, p1 = 0.f;
#pragma unroll
        for (int m = 0; m < 3; m++) {
            float c[4] = {0.f, 0.f, 0.f, 0.f};
#pragma unroll
            for (int kt = 0; kt < 8; kt++) mma_tf32(c, Ea[m][kt], Bf[kt]);
            int r1 = 16 * m + g, r2 = r1 + 8;
            float z0 = fmaxf(c[0] + Gr[m][0] + f0, 0.f);
            float z1 = fmaxf(c[1] + Gr[m][1] + f1, 0.f);
            __stcs(reinterpret_cast<float2*>(zp + r1 * 64 + o0), make_float2(z0, z1));
            zj[m][0] += z0; zj[m][1] += z1; p0 += z0; p1 += z1;
            if (m < 2) {
                float z2 = fmaxf(c[2] + Gr[m][2] + f0, 0.f);
                float z3 = fmaxf(c[3] + Gr[m][3] + f1, 0.f);
                __stcs(reinterpret_cast<float2*>(zp + r2 * 64 + o0), make_float2(z2, z3));
                zj[m][2] += z2; zj[m][3] += z3; p0 += z2; p1 += z3;
            }
        }
        // zsk: reduce over k (rows) = over groupID lanes
#pragma unroll
        for (int off = 4; off < 32; off <<= 1) {
            p0 += __shfl_xor_sync(0xffffffffu, p0, off);
            p1 += __shfl_xor_sync(0xffffffffu, p1, off);
        }
        if (g == 0)
            *reinterpret_cast<float2*>(&g_zsk[((b * 40 + i) * 40 + j) * 64 + o0]) =
                make_float2(p0, p1);
    }
    // zsj writes (sum over j, per (k,o))
#pragma unroll
    for (int m = 0; m < 3; m++) {
        int r1 = 16 * m + g, r2 = r1 + 8;
        *reinterpret_cast<float2*>(&g_zsj[((b * 40 + i) * 40 + r1) * 64 + o0]) =
            make_float2(zj[m][0], zj[m][1]);
        if (m < 2)
            *reinterpret_cast<float2*>(&g_zsj[((b * 40 + i) * 40 + r2) * 64 + o0]) =
                make_float2(zj[m][2], zj[m][3]);
    }
}

// ---------------- K5: zsi = sum over i of z (coalesced stream) --------------
__global__ void k_sums() {
    int j = blockIdx.x, b = blockIdx.y;    // grid (40,16)
    int tid = threadIdx.x;
    float acc[10];
#pragma unroll
    for (int q = 0; q < 10; q++) acc[q] = 0.f;
    for (int i = 0; i < 40; i++) {
        const float* p = g_z + (((long long)((b * 40 + i) * 40 + j)) * 2560);
#pragma unroll
        for (int q = 0; q < 10; q++) acc[q] += __ldcs(p + tid + q * 256);
    }
    float* dst = g_zsi + ((long long)(b * 40 + j)) * 2560;
#pragma unroll
    for (int q = 0; q < 10; q++) dst[tid + q * 256] = acc[q];
}

// ---------------- K5b: c1/c2/c3 = zsum_* @ V_m ------------------------------
__global__ void k_cproj(const float* __restrict__ V, int which) {
    const float* src = (which == 0) ? g_zsi : (which == 1) ? g_zsj : g_zsk;
    float* dst       = (which == 0) ? g_c1  : (which == 1) ? g_c2  : g_c3;
    const float* Wm = V + (which + 1) * 2048;   // V1 / V2 / V3
    __shared__ float rows[512];            // 8 rows x 64
    __shared__ float ws[2048];             // 64 x 32
    int r0 = blockIdx.x * 8;
    for (int t = threadIdx.x; t < 2048; t += 256) ws[t] = Wm[t];
    for (int t = threadIdx.x; t < 512; t += 256) rows[t] = src[r0 * 64 + t];
    __syncthreads();
    int o = threadIdx.x & 31, rr = threadIdx.x >> 5;
    float acc = 0.f;
#pragma unroll
    for (int d = 0; d < 64; d++) acc = fmaf(rows[rr * 64 + d], ws[d * 32 + o], acc);
    dst[(r0 + rr) * 32 + o] = acc;
}

// ---------------- K5c: pair/total sums -> c4..c7 ----------------------------
__global__ void k_cpair(const float* __restrict__ V) {
    int b = blockIdx.x;                    // 16 blocks, 256 threads
    __shared__ float zij[2560];            // [k][d]
    __shared__ float zik[2560];            // [j][d]
    __shared__ float zjk[2560];            // [i][d]
    __shared__ float zs[64];
    int d = threadIdx.x & 63, g = threadIdx.x >> 6;
    for (int q = 0; q < 10; q++) {
        int k = g * 10 + q;
        float s = 0.f;
#pragma unroll 8
        for (int j = 0; j < 40; j++) s += g_zsi[((b * 40 + j) * 40 + k) * 64 + d];
        zij[k * 64 + d] = s;
    }
    for (int q = 0; q < 10; q++) {
        int j = g * 10 + q;
        float s = 0.f;
#pragma unroll 8
        for (int k = 0; k < 40; k++) s += g_zsi[((b * 40 + j) * 40 + k) * 64 + d];
        zik[j * 64 + d] = s;
    }
    for (int q = 0; q < 10; q++) {
        int i = g * 10 + q;
        float s = 0.f;
#pragma unroll 8
        for (int k = 0; k < 40; k++) s += g_zsj[((b * 40 + i) * 40 + k) * 64 + d];
        zjk[i * 64 + d] = s;
    }
    __syncthreads();
    if (threadIdx.x < 64) {
        float s = 0.f;
#pragma unroll
        for (int k = 0; k < 40; k++) s += zij[k * 64 + threadIdx.x];
        zs[threadIdx.x] = s;
    }
    __syncthreads();
    const float* V4 = V + 4 * 2048;
    const float* V5 = V + 5 * 2048;
    const float* V6 = V + 6 * 2048;
    const float* V7 = V + 7 * 2048;
    int o = threadIdx.x & 31, kg = threadIdx.x >> 5;   // 8 groups of 5
    for (int q = 0; q < 5; q++) {
        int k = kg * 5 + q;
        float a4 = 0.f, a5 = 0.f, a6 = 0.f;
#pragma unroll 8
        for (int dd = 0; dd < 64; dd++) {
            a4 = fmaf(zij[k * 64 + dd], V4[dd * 32 + o], a4);
            a5 = fmaf(zik[k * 64 + dd], V5[dd * 32 + o], a5);
            a6 = fmaf(zjk[k * 64 + dd], V6[dd * 32 + o], a6);
        }
        g_c4[(b * 40 + k) * 32 + o] = a4;
        g_c5[(b * 40 + k) * 32 + o] = a5;
        g_c6[(b * 40 + k) * 32 + o] = a6;
    }
    if (threadIdx.x < 32) {
        float a = 0.f;
#pragma unroll 8
        for (int dd = 0; dd < 64; dd++) a = fmaf(zs[dd], V7[dd * 32 + threadIdx.x], a);
        g_c7[b * 32 + threadIdx.x] = a;
    }
}

// ---------------- K6: eq2 + relu + sum over j,k, block per (b,i) ------------
__global__ void __launch_bounds__(256, 2)
k_eq2(const float* __restrict__ V, const float* __restrict__ b2) {
    int i = blockIdx.x, b = blockIdx.y;
    __shared__ __align__(16) float zrow[2560];
    __shared__ float c1row[1280];
    __shared__ float c2s[1280], c3s[1280], c4s[1280], c5s[1280];
    __shared__ float cb[32];
    __shared__ float red[256];
    int tid = threadIdx.x;
    for (int t = tid; t < 1280; t += 256) {
        c2s[t] = g_c2[(b * 40 + i) * 1280 + t];
        c3s[t] = g_c3[(b * 40 + i) * 40 * 32 + t];
        c4s[t] = g_c4[b * 1280 + t];
        c5s[t] = g_c5[b * 1280 + t];
    }
    int o = tid & 31, kq = tid >> 5;       // 8 groups of 5 k
    if (tid < 32)
        cb[tid] = g_c6[(b * 40 + i) * 32 + tid] + g_c7[b * 32 + tid] + b2[tid];
    float Vreg[64];
#pragma unroll
    for (int d = 0; d < 64; d++) Vreg[d] = V[d * 32 + o];   // V0
    __syncthreads();

    float part = 0.f;
    long long zbi = ((long long)(b * 40 + i)) * 40 * 2560;
    for (int j = 0; j < 40; j++) {
        const float* zp = g_z + zbi + (long long)j * 2560;
        const float* c1p = g_c1 + (b * 40 + j) * 1280;
#pragma unroll
        for (int q = 0; q < 10; q++) zrow[tid + q * 256] = __ldcs(zp + tid + q * 256);
#pragma unroll
        for (int q = 0; q < 5; q++) c1row[tid + q * 256] = c1p[tid + q * 256];
        __syncthreads();
        float cf = cb[o] + c3s[j * 32 + o] + c5s[j * 32 + o];
        for (int q = 0; q < 5; q++) {
            int k = kq * 5 + q;
            const float4* z4 = reinterpret_cast<const float4*>(&zrow[k * 64]);
            float acc = cf + c1row[k * 32 + o] + c2s[k * 32 + o] + c4s[k * 32 + o];
#pragma unroll
            for (int t = 0; t < 16; t++) {
                float4 v = z4[t];
                acc = fmaf(v.x, Vreg[4 * t + 0], acc);
                acc = fmaf(v.y, Vreg[4 * t + 1], acc);
                acc = fmaf(v.z, Vreg[4 * t + 2], acc);
                acc = fmaf(v.w, Vreg[4 * t + 3], acc);
            }
            part += fmaxf(acc, 0.f);
        }
        __syncthreads();
    }
    red[tid] = part;
    __syncthreads();
    if (tid < 32) {
        float s = 0.f;
#pragma unroll
        for (int g = 0; g < 8; g++) s += red[g * 32 + tid];
        g_part[(b * 40 + i) * 32 + tid] = s;
    }
}

// ---------------- K7: final reduce + out projection -------------------------
__global__ void k_final(const float* __restrict__ ow, const float* __restrict__ ob,
                        float* __restrict__ out) {
    int b = blockIdx.x;                    // 16 blocks, 256 threads
    __shared__ float red[256];
    int o = threadIdx.x & 31, g = threadIdx.x >> 5;
    float s = 0.f;
    for (int i = g; i < 40; i += 8) s += g_part[(b * 40 + i) * 32 + o];
    red[threadIdx.x] = s;
    __syncthreads();
    if (threadIdx.x < 32) {
        float tot = 0.f;
#pragma unroll
        for (int q = 0; q < 8; q++) tot += red[q * 32 + threadIdx.x];
        tot = fmaxf(tot, 0.f);
        float v = tot * ow[threadIdx.x];
#pragma unroll
        for (int off = 16; off; off >>= 1) v += __shfl_down_sync(0xffffffffu, v, off);
        if (threadIdx.x == 0) out[b] = v + ob[0];
    }
}

// ---------------- launcher ---------------------------------------------------
extern "C" void kernel_launch(void* const* d_in, const int* in_sizes, int n_in,
                              void* d_out, int out_size) {
    const float* x   = (const float*)d_in[0];
    const float* c1w = (const float*)d_in[1];
    const float* c1b = (const float*)d_in[2];
    const float* c2w = (const float*)d_in[3];
    const float* c2b = (const float*)d_in[4];
    const float* fcw = (const float*)d_in[5];
    const float* fcb = (const float*)d_in[6];
    const float* e1w = (const float*)d_in[7];
    const float* e1b = (const float*)d_in[8];
    const float* e2w = (const float*)d_in[9];
    const float* e2b = (const float*)d_in[10];
    const float* ow  = (const float*)d_in[11];
    const float* ob  = (const float*)d_in[12];
    float* out = (float*)d_out;

    k_conv1<<<640, 256>>>(x, c1w, c1b);
    k_conv2<<<640, 256>>>(c2w, c2b);
    k_fc<<<160, 256>>>(fcw, fcb);
    k_S<<<16, 64>>>();
    k_pre1<<<16, 64>>>(e1w, e1b);
    dim3 gbi(40, 16);
    k_eq1<<<gbi, 256>>>(e1w);
    k_sums<<<gbi, 256>>>();
    k_cproj<<<3200, 256>>>(e2w, 0);
    k_cproj<<<3200, 256>>>(e2w, 1);
    k_cproj<<<3200, 256>>>(e2w, 2);
    k_cpair<<<16, 256>>>(e2w);
    k_eq2<<<gbi, 256>>>(e2w, e2b);
    k_final<<<16, 256>>>(ow, ob, out);
}